// round 14
// baseline (speedup 1.0000x reference)
#include <cuda_runtime.h>
#include <math.h>
#include <stdint.h>

// Problem constants
#define BB 8
#define TT 448
#define SS 1500
#define DD 1024
#define HH 16
#define DH 64
#define OUT_ELEMS (BB*TT*DD)

// Scratch
__device__ float g_q  [BB*TT*DD];
__device__ float g_k  [BB*SS*DD];
__device__ float g_v  [BB*SS*DD];
__device__ float g_wv [BB*TT*DD];
__device__ float g_xt [BB*TT*DD];
__device__ float g_xat[BB*SS*DD];
__device__ float g_Wqt[DD*DD];
__device__ float g_Wkt[DD*DD];
__device__ float g_Wvt[DD*DD];
__device__ float g_Wot[DD*DD];

// ---------------------------------------------------------------------------
// helpers
// ---------------------------------------------------------------------------
__device__ __forceinline__ uint32_t f2tf32(float f) {
    uint32_t r;
    asm("cvt.rna.tf32.f32 %0, %1;" : "=r"(r) : "f"(f));
    return r;
}
__device__ __forceinline__ float4 cvt4(float4 v) {
    return make_float4(__uint_as_float(f2tf32(v.x)), __uint_as_float(f2tf32(v.y)),
                       __uint_as_float(f2tf32(v.z)), __uint_as_float(f2tf32(v.w)));
}
__device__ __forceinline__ void mma8(float* c, const uint32_t* a, const uint32_t* b) {
    asm volatile("mma.sync.aligned.m16n8k8.row.col.f32.tf32.tf32.f32 "
        "{%0,%1,%2,%3}, {%4,%5,%6,%7}, {%8,%9}, {%0,%1,%2,%3};"
        : "+f"(c[0]), "+f"(c[1]), "+f"(c[2]), "+f"(c[3])
        : "r"(a[0]), "r"(a[1]), "r"(a[2]), "r"(a[3]), "r"(b[0]), "r"(b[1]));
}
__device__ __forceinline__ void cp16(const float* s, const float* g) {
    uint32_t sa = (uint32_t)__cvta_generic_to_shared((void*)s);
    asm volatile("cp.async.cg.shared.global [%0], [%1], 16;" :: "r"(sa), "l"(g));
}
__device__ __forceinline__ void ldsm4(uint32_t* r, uint32_t saddr) {
    asm volatile("ldmatrix.sync.aligned.m8n8.x4.shared.b16 {%0,%1,%2,%3}, [%4];"
        : "=r"(r[0]), "=r"(r[1]), "=r"(r[2]), "=r"(r[3]) : "r"(saddr));
}
// streaming (evict-first) float2 store: qk is write-once, never re-read
__device__ __forceinline__ void stcs2(float* p, float x, float y) {
    asm volatile("st.global.cs.v2.f32 [%0], {%1,%2};" :: "l"(p), "f"(x), "f"(y) : "memory");
}

// ---------------------------------------------------------------------------
// Single fused tf32 pre-round for all 6 operand tensors (elementwise).
// ---------------------------------------------------------------------------
#define NX (BB*TT*DD/4)
#define NA (BB*SS*DD/4)
#define NW (DD*DD/4)

__global__ void cvt_all(const float* __restrict__ x,  float* __restrict__ xt,
                        const float* __restrict__ xa, float* __restrict__ xat,
                        const float* __restrict__ Wq, float* __restrict__ Wqt,
                        const float* __restrict__ Wk, float* __restrict__ Wkt,
                        const float* __restrict__ Wv, float* __restrict__ Wvt,
                        const float* __restrict__ Wo, float* __restrict__ Wot)
{
    int i = blockIdx.x * blockDim.x + threadIdx.x;
    const float4* src; float4* dst; int j = i;
    if (j < NX)            { src = (const float4*)x;  dst = (float4*)xt; }
    else if ((j -= NX) < NA) { src = (const float4*)xa; dst = (float4*)xat; }
    else {
        j -= NA;
        int w = j / NW; j -= w * NW;
        switch (w) {
            case 0: src = (const float4*)Wq; dst = (float4*)Wqt; break;
            case 1: src = (const float4*)Wk; dst = (float4*)Wkt; break;
            case 2: src = (const float4*)Wv; dst = (float4*)Wvt; break;
            default: if (w > 3) return;
                    src = (const float4*)Wo; dst = (float4*)Wot; break;
        }
    }
    dst[j] = cvt4(src[j]);
}

// ---------------------------------------------------------------------------
// tf32 GEMM (R13, measured-best): 128x128 tile, 4 warps, warp 64x64,
// 5-stage BK=16 cp.async pipeline, full-stage fragment preload.
// ---------------------------------------------------------------------------
#define STAGES 5
#define GASTR 20
#define GBSTR 136
#define A_STG (128*GASTR)
#define B_STG (16*GBSTR)

__global__ __launch_bounds__(128, 2) void gemm_tf32(
    const float* __restrict__ A, const float* __restrict__ Bm,
    const float* __restrict__ bias, float* __restrict__ C,
    int M, int N, int K, float alpha, int round_out)
{
    extern __shared__ float smg[];
    float* As = smg;
    float* Bs = smg + STAGES * A_STG;

    const int tid  = threadIdx.x;
    const int warp = tid >> 5, lane = tid & 31;
    const int wm = warp >> 1, wn = warp & 1;
    const int g  = lane >> 2, tg = lane & 3;
    const int m0 = blockIdx.y * 128, n0 = blockIdx.x * 128;

    const int ar0 = tid >> 2, ac0 = (tid & 3) << 2;
    const int br0 = tid >> 5, bc0 = lane << 2;

    float acc[4][8][4];
#pragma unroll
    for (int mi = 0; mi < 4; mi++)
#pragma unroll
        for (int nj = 0; nj < 8; nj++)
#pragma unroll
            for (int r = 0; r < 4; r++) acc[mi][nj][r] = 0.f;

    const int nt = K >> 4;

    auto issue_tile = [&](int t, int stg) {
        const int k0 = t << 4;
        float* as = As + stg * A_STG;
        float* bs = Bs + stg * B_STG;
#pragma unroll
        for (int i = 0; i < 4; i++) {
            int ra = ar0 + i * 32;
            int gr = min(m0 + ra, M - 1);
            cp16(as + ra * GASTR + ac0, A + (size_t)gr * K + k0 + ac0);
            int rb = br0 + i * 4;
            cp16(bs + rb * GBSTR + bc0, Bm + (size_t)(k0 + rb) * N + n0 + bc0);
        }
    };

#pragma unroll
    for (int t = 0; t < STAGES - 1; t++) {
        issue_tile(t, t);
        asm volatile("cp.async.commit_group;");
    }

    for (int t = 0; t < nt; t++) {
        asm volatile("cp.async.wait_group %0;" :: "n"(STAGES - 2));
        __syncthreads();

        const float* as = As + (t % STAGES) * A_STG;
        const float* bs = Bs + (t % STAGES) * B_STG;

        // ---- load ALL fragments for this stage (both kk halves) ----
        uint32_t af[2][4][4], bf[2][8][2];
#pragma unroll
        for (int h = 0; h < 2; h++) {
            const int kk = h * 8;
#pragma unroll
            for (int mi = 0; mi < 4; mi++) {
                int row = wm * 64 + mi * 16 + g;
                af[h][mi][0] = __float_as_uint(as[row * GASTR + kk + tg]);
                af[h][mi][1] = __float_as_uint(as[(row + 8) * GASTR + kk + tg]);
                af[h][mi][2] = __float_as_uint(as[row * GASTR + kk + tg + 4]);
                af[h][mi][3] = __float_as_uint(as[(row + 8) * GASTR + kk + tg + 4]);
            }
#pragma unroll
            for (int nj = 0; nj < 8; nj++) {
                int col = wn * 64 + nj * 8 + g;
                bf[h][nj][0] = __float_as_uint(bs[(kk + tg) * GBSTR + col]);
                bf[h][nj][1] = __float_as_uint(bs[(kk + tg + 4) * GBSTR + col]);
            }
        }

        if (t + STAGES - 1 < nt)
            issue_tile(t + STAGES - 1, (t + STAGES - 1) % STAGES);
        asm volatile("cp.async.commit_group;");

        // ---- uninterrupted 64-HMMA burst ----
#pragma unroll
        for (int h = 0; h < 2; h++)
#pragma unroll
            for (int mi = 0; mi < 4; mi++)
#pragma unroll
                for (int nj = 0; nj < 8; nj++)
                    mma8(acc[mi][nj], af[h][mi], bf[h][nj]);
    }

    // Epilogue
#pragma unroll
    for (int nj = 0; nj < 8; nj++) {
        int col = n0 + wn * 64 + nj * 8 + tg * 2;
        float2 bv = make_float2(0.f, 0.f);
        if (bias) bv = *(const float2*)(bias + col);
#pragma unroll
        for (int mi = 0; mi < 4; mi++) {
            int r0 = m0 + wm * 64 + mi * 16 + g;
            if (r0 < M) {
                float ox = (acc[mi][nj][0] + bv.x) * alpha;
                float oy = (acc[mi][nj][1] + bv.y) * alpha;
                if (round_out) { ox = __uint_as_float(f2tf32(ox)); oy = __uint_as_float(f2tf32(oy)); }
                *(float2*)(C + (size_t)r0 * N + col) = make_float2(ox, oy);
            }
            if (r0 + 8 < M) {
                float ox = (acc[mi][nj][2] + bv.x) * alpha;
                float oy = (acc[mi][nj][3] + bv.y) * alpha;
                if (round_out) { ox = __uint_as_float(f2tf32(ox)); oy = __uint_as_float(f2tf32(oy)); }
                *(float2*)(C + (size_t)(r0 + 8) * N + col) = make_float2(ox, oy);
            }
        }
    }
}

// ---------------------------------------------------------------------------
// tf32 flash attention: 4 warps, warp owns 16 q-rows x 64 s-cols.
// cp.async K double-buffer / V single-buffer + ldmatrix Q/K/P frags.
// qk stores use st.global.cs (write-once, evict-first). Full-chunk (sc==64)
// path specialized: unpredicated staging + stores.
// ---------------------------------------------------------------------------
#define KSTR 68
#define VSTR 72
#define PQSTR 68
#define NCHUNK ((SS + 63) / 64)   // 24

__global__ __launch_bounds__(128) void attn_tf32(
    const float* __restrict__ q, const float* __restrict__ k,
    const float* __restrict__ v, float* __restrict__ qk_out,
    float* __restrict__ wv_out)
{
    extern __shared__ float sm[];
    float* Ks = sm;                    // [2][64][68]
    float* Vs = Ks + 2 * 64 * KSTR;    // [64][72]
    float* Ps = Vs + 64 * VSTR;        // [64][68]  (also Q staging)

    const int tid  = threadIdx.x;
    const int warp = tid >> 5, lane = tid & 31;
    const int g  = lane >> 2, tg = lane & 3;
    const int bh = blockIdx.y;
    const int b  = bh >> 4, h = bh & 15;
    const int t0 = blockIdx.x * 64;
    const int rw = warp * 16;
    const int grow0 = t0 + rw + g;

    const int sr = tid >> 4, scol4 = (tid & 15) << 2;

    const uint32_t ps_u = (uint32_t)__cvta_generic_to_shared((void*)Ps)
        + (((rw + (lane & 15)) * PQSTR + (lane >> 4) * 4) << 2);
    const uint32_t ks_base = (uint32_t)__cvta_generic_to_shared((void*)Ks)
        + ((((lane & 7) + ((lane & 16) ? 8 : 0)) * KSTR + ((lane & 8) ? 4 : 0)) << 2);

    auto issueK = [&](int s0, int buf, bool full) {
        float* dst = Ks + buf * 64 * KSTR;
#pragma unroll
        for (int i = 0; i < 8; i++) {
            int r = sr + i * 8;
            if (full || s0 + r < SS)
                cp16(dst + r * KSTR + scol4,
                     k + (size_t)(b * SS + s0 + r) * DD + h * DH + scol4);
        }
    };
    auto issueV = [&](int s0, bool full) {
#pragma unroll
        for (int i = 0; i < 8; i++) {
            int r = sr + i * 8;
            if (full || s0 + r < SS)
                cp16(Vs + r * VSTR + scol4,
                     v + (size_t)(b * SS + s0 + r) * DD + h * DH + scol4);
        }
    };

    // ---- stage Q through smem (already tf32), pull frags via ldmatrix ----
#pragma unroll
    for (int i = 0; i < 8; i++) {
        int idx = tid + i * 128;
        int r = idx >> 4, c = (idx & 15) << 2;
        float4 val = *(const float4*)(q + (size_t)(b * TT + t0 + r) * DD + h * DH + c);
        *(float4*)(Ps + r * PQSTR + c) = val;
    }
    __syncthreads();

    uint32_t qf[8][4];
#pragma unroll
    for (int kk = 0; kk < 8; kk++)
        ldsm4(qf[kk], ps_u + ((kk * 8) << 2));

    float o[8][4];
#pragma unroll
    for (int nj = 0; nj < 8; nj++)
#pragma unroll
        for (int r = 0; r < 4; r++) o[nj][r] = 0.f;

    float m0s = -INFINITY, m1s = -INFINITY, l0s = 0.f, l1s = 0.f;

    __syncthreads();

    issueK(0, 0, true);
    asm volatile("cp.async.commit_group;");

    for (int ci = 0; ci < NCHUNK; ci++) {
        const int s0 = ci * 64;
        const int sc = min(64, SS - s0);
        const bool full = (sc == 64);
        const uint32_t ks_u = ks_base + (uint32_t)((ci & 1) * 64 * KSTR * 4);

        issueV(s0, full);
        asm volatile("cp.async.commit_group;");
        if (ci + 1 < NCHUNK) issueK(s0 + 64, (ci + 1) & 1, s0 + 128 <= SS);
        asm volatile("cp.async.commit_group;");

        asm volatile("cp.async.wait_group %0;" :: "n"(2));   // K(ci) arrived
        __syncthreads();

        // ---- QK^T via ldmatrix K-frags ----
        float qa[8][4];
#pragma unroll
        for (int nj = 0; nj < 8; nj++)
#pragma unroll
            for (int r = 0; r < 4; r++) qa[nj][r] = 0.f;

#pragma unroll
        for (int kk = 0; kk < 8; kk++) {
            uint32_t bfr[4][4];
#pragma unroll
            for (int p = 0; p < 4; p++)
                ldsm4(bfr[p], ks_u + ((p * 16 * KSTR + kk * 8) << 2));
#pragma unroll
            for (int p = 0; p < 4; p++) {
                mma8(qa[2 * p],     qf[kk], &bfr[p][0]);
                mma8(qa[2 * p + 1], qf[kk], &bfr[p][2]);
            }
        }

        // ---- write raw logits (streaming stores); mask out-of-range ----
        {
            float* rowp = qk_out + ((size_t)bh * TT + grow0) * SS + s0;
            if (full) {
#pragma unroll
                for (int nj = 0; nj < 8; nj++) {
                    int col = nj * 8 + tg * 2;
                    stcs2(rowp + col,          qa[nj][0], qa[nj][1]);
                    stcs2(rowp + 8 * SS + col, qa[nj][2], qa[nj][3]);
                }
            } else {
#pragma unroll
                for (int nj = 0; nj < 8; nj++) {
                    int col = nj * 8 + tg * 2;
                    if (col < sc) {
                        stcs2(rowp + col,          qa[nj][0], qa[nj][1]);
                        stcs2(rowp + 8 * SS + col, qa[nj][2], qa[nj][3]);
                    } else {
                        qa[nj][0] = qa[nj][1] = -1e30f;
                        qa[nj][2] = qa[nj][3] = -1e30f;
                    }
                }
            }
        }

        // ---- warp-local online softmax ----
        float mx0 = -INFINITY, mx1 = -INFINITY;
#pragma unroll
        for (int nj = 0; nj < 8; nj++) {
            mx0 = fmaxf(mx0, fmaxf(qa[nj][0], qa[nj][1]));
            mx1 = fmaxf(mx1, fmaxf(qa[nj][2], qa[nj][3]));
        }
        mx0 = fmaxf(mx0, __shfl_xor_sync(0xffffffffu, mx0, 1));
        mx0 = fmaxf(mx0, __shfl_xor_sync(0xffffffffu, mx0, 2));
        mx1 = fmaxf(mx1, __shfl_xor_sync(0xffffffffu, mx1, 1));
        mx1 = fmaxf(mx1, __shfl_xor_sync(0xffffffffu, mx1, 2));

        float mn0 = fmaxf(m0s, mx0), mn1 = fmaxf(m1s, mx1);
        float c0 = __expf(m0s - mn0), c1 = __expf(m1s - mn1);
        m0s = mn0; m1s = mn1;

        float s0r = 0.f, s1r = 0.f;
#pragma unroll
        for (int nj = 0; nj < 8; nj++) {
            float p0 = __expf(qa[nj][0] - mn0);
            float p1 = __expf(qa[nj][1] - mn0);
            float p2 = __expf(qa[nj][2] - mn1);
            float p3 = __expf(qa[nj][3] - mn1);
            s0r += p0 + p1; s1r += p2 + p3;
            qa[nj][0] = __uint_as_float(f2tf32(p0));
            qa[nj][1] = __uint_as_float(f2tf32(p1));
            qa[nj][2] = __uint_as_float(f2tf32(p2));
            qa[nj][3] = __uint_as_float(f2tf32(p3));
        }
        s0r += __shfl_xor_sync(0xffffffffu, s0r, 1);
        s0r += __shfl_xor_sync(0xffffffffu, s0r, 2);
        s1r += __shfl_xor_sync(0xffffffffu, s1r, 1);
        s1r += __shfl_xor_sync(0xffffffffu, s1r, 2);
        l0s = l0s * c0 + s0r;
        l1s = l1s * c1 + s1r;

#pragma unroll
        for (int nj = 0; nj < 8; nj++) {
            o[nj][0] *= c0; o[nj][1] *= c0;
            o[nj][2] *= c1; o[nj][3] *= c1;
        }

        // ---- P -> per-warp smem slab ----
#pragma unroll
        for (int nj = 0; nj < 8; nj++) {
            int col = nj * 8 + tg * 2;
            *(float2*)(Ps + (rw + g) * PQSTR + col)     = make_float2(qa[nj][0], qa[nj][1]);
            *(float2*)(Ps + (rw + g + 8) * PQSTR + col) = make_float2(qa[nj][2], qa[nj][3]);
        }
        __syncwarp();

        asm volatile("cp.async.wait_group %0;" :: "n"(1));   // V(ci) arrived
        __syncthreads();

        // ---- PV: A-frags via ldmatrix on Ps, V-frags plain LDS ----
#pragma unroll
        for (int kk = 0; kk < 8; kk++) {
            uint32_t af[4], bfr[8][2];
            ldsm4(af, ps_u + ((kk * 8) << 2));
#pragma unroll
            for (int nj = 0; nj < 8; nj++) {
                int dcol = nj * 8 + g;
                bfr[nj][0] = __float_as_uint(Vs[(kk * 8 + tg) * VSTR + dcol]);
                bfr[nj][1] = __float_as_uint(Vs[(kk * 8 + tg + 4) * VSTR + dcol]);
            }
#pragma unroll
            for (int nj = 0; nj < 8; nj++)
                mma8(o[nj], af, bfr[nj]);
        }
        __syncthreads();
    }

    // ---- normalize, write wv (tf32-rounded: consumed by out-GEMM) ----
    float inv0 = 1.f / l0s, inv1 = 1.f / l1s;
    size_t obase = (size_t)(b * TT + grow0) * DD + h * DH;
#pragma unroll
    for (int nj = 0; nj < 8; nj++) {
        int col = nj * 8 + tg * 2;
        float2 r0 = make_float2(__uint_as_float(f2tf32(o[nj][0] * inv0)),
                                __uint_as_float(f2tf32(o[nj][1] * inv0)));
        float2 r1 = make_float2(__uint_as_float(f2tf32(o[nj][2] * inv1)),
                                __uint_as_float(f2tf32(o[nj][3] * inv1)));
        *(float2*)(wv_out + obase + col)          = r0;
        *(float2*)(wv_out + obase + 8 * DD + col) = r1;
    }
}

// ---------------------------------------------------------------------------
extern "C" void kernel_launch(void* const* d_in, const int* in_sizes, int n_in,
                              void* d_out, int out_size)
{
    const float* x  = (const float*)d_in[0];
    const float* xa = (const float*)d_in[1];
    const float* Wq = (const float*)d_in[2];
    const float* bq = (const float*)d_in[3];
    const float* Wk = (const float*)d_in[4];
    const float* Wv = (const float*)d_in[5];
    const float* bv = (const float*)d_in[6];
    const float* Wo = (const float*)d_in[7];
    const float* bo = (const float*)d_in[8];

    float* out = (float*)d_out;               // [8,448,1024]
    float* qk  = out + OUT_ELEMS;             // [8,16,448,1500]

    float *q_s, *k_s, *v_s, *wv_s, *xt, *xat, *Wqt, *Wkt, *Wvt, *Wot;
    cudaGetSymbolAddress((void**)&q_s,  g_q);
    cudaGetSymbolAddress((void**)&k_s,  g_k);
    cudaGetSymbolAddress((void**)&v_s,  g_v);
    cudaGetSymbolAddress((void**)&wv_s, g_wv);
    cudaGetSymbolAddress((void**)&xt,   g_xt);
    cudaGetSymbolAddress((void**)&xat,  g_xat);
    cudaGetSymbolAddress((void**)&Wqt,  g_Wqt);
    cudaGetSymbolAddress((void**)&Wkt,  g_Wkt);
    cudaGetSymbolAddress((void**)&Wvt,  g_Wvt);
    cudaGetSymbolAddress((void**)&Wot,  g_Wot);

    const float scale = 0.3535533905932738f;  // 64^-0.25

    // ---- single fused pre-round of all operands ----
    {
        const int thr = 256;
        int total = NX + NA + 4 * NW;
        cvt_all<<<(total + thr - 1) / thr, thr>>>(x, xt, xa, xat,
                                                  Wq, Wqt, Wk, Wkt, Wv, Wvt, Wo, Wot);
    }

    static const size_t gemm_smem = (size_t)(STAGES * (A_STG + B_STG)) * sizeof(float); // 94720
    cudaFuncSetAttribute(gemm_tf32, cudaFuncAttributeMaxDynamicSharedMemorySize, (int)gemm_smem);

    dim3 blk(128);
    gemm_tf32<<<dim3(DD/128, (BB*TT + 127)/128), blk, gemm_smem>>>(xt,  Wqt, bq,      q_s, BB*TT, DD, DD, scale, 1);
    gemm_tf32<<<dim3(DD/128, (BB*SS + 127)/128), blk, gemm_smem>>>(xat, Wkt, nullptr, k_s, BB*SS, DD, DD, scale, 1);
    gemm_tf32<<<dim3(DD/128, (BB*SS + 127)/128), blk, gemm_smem>>>(xat, Wvt, bv,      v_s, BB*SS, DD, DD, 1.0f, 1);

    static const size_t attn_smem =
        (2 * 64 * KSTR + 64 * VSTR + 64 * PQSTR) * sizeof(float);  // 70656
    cudaFuncSetAttribute(attn_tf32, cudaFuncAttributeMaxDynamicSharedMemorySize, (int)attn_smem);
    attn_tf32<<<dim3(TT/64, BB*HH), dim3(128), attn_smem>>>(q_s, k_s, v_s, qk, wv_s);

    gemm_tf32<<<dim3(DD/128, (BB*TT + 127)/128), blk, gemm_smem>>>(wv_s, Wot, bo, out, BB*TT, DD, DD, 1.0f, 0);
}

// round 15
// speedup vs baseline: 1.0163x; 1.0163x over previous
#include <cuda_runtime.h>
#include <math.h>
#include <stdint.h>

// Problem constants
#define BB 8
#define TT 448
#define SS 1500
#define DD 1024
#define HH 16
#define DH 64
#define OUT_ELEMS (BB*TT*DD)

// Scratch
__device__ float g_q  [BB*TT*DD];
__device__ float g_k  [BB*SS*DD];
__device__ float g_v  [BB*SS*DD];
__device__ float g_wv [BB*TT*DD];
__device__ float g_xt [BB*TT*DD];
__device__ float g_xat[BB*SS*DD];
__device__ float g_Wqt[DD*DD];
__device__ float g_Wkt[DD*DD];
__device__ float g_Wvt[DD*DD];
__device__ float g_Wot[DD*DD];

// ---------------------------------------------------------------------------
// helpers
// ---------------------------------------------------------------------------
__device__ __forceinline__ uint32_t f2tf32(float f) {
    uint32_t r;
    asm("cvt.rna.tf32.f32 %0, %1;" : "=r"(r) : "f"(f));
    return r;
}
__device__ __forceinline__ float4 cvt4(float4 v) {
    return make_float4(__uint_as_float(f2tf32(v.x)), __uint_as_float(f2tf32(v.y)),
                       __uint_as_float(f2tf32(v.z)), __uint_as_float(f2tf32(v.w)));
}
__device__ __forceinline__ void mma8(float* c, const uint32_t* a, const uint32_t* b) {
    asm volatile("mma.sync.aligned.m16n8k8.row.col.f32.tf32.tf32.f32 "
        "{%0,%1,%2,%3}, {%4,%5,%6,%7}, {%8,%9}, {%0,%1,%2,%3};"
        : "+f"(c[0]), "+f"(c[1]), "+f"(c[2]), "+f"(c[3])
        : "r"(a[0]), "r"(a[1]), "r"(a[2]), "r"(a[3]), "r"(b[0]), "r"(b[1]));
}
__device__ __forceinline__ void cp16(const float* s, const float* g) {
    uint32_t sa = (uint32_t)__cvta_generic_to_shared((void*)s);
    asm volatile("cp.async.cg.shared.global [%0], [%1], 16;" :: "r"(sa), "l"(g));
}
__device__ __forceinline__ void ldsm4(uint32_t* r, uint32_t saddr) {
    asm volatile("ldmatrix.sync.aligned.m8n8.x4.shared.b16 {%0,%1,%2,%3}, [%4];"
        : "=r"(r[0]), "=r"(r[1]), "=r"(r[2]), "=r"(r[3]) : "r"(saddr));
}

// ---------------------------------------------------------------------------
// Single fused tf32 pre-round for all 6 operand tensors (elementwise).
// ---------------------------------------------------------------------------
#define NX (BB*TT*DD/4)
#define NA (BB*SS*DD/4)
#define NW (DD*DD/4)

__global__ void cvt_all(const float* __restrict__ x,  float* __restrict__ xt,
                        const float* __restrict__ xa, float* __restrict__ xat,
                        const float* __restrict__ Wq, float* __restrict__ Wqt,
                        const float* __restrict__ Wk, float* __restrict__ Wkt,
                        const float* __restrict__ Wv, float* __restrict__ Wvt,
                        const float* __restrict__ Wo, float* __restrict__ Wot)
{
    int i = blockIdx.x * blockDim.x + threadIdx.x;
    const float4* src; float4* dst; int j = i;
    if (j < NX)            { src = (const float4*)x;  dst = (float4*)xt; }
    else if ((j -= NX) < NA) { src = (const float4*)xa; dst = (float4*)xat; }
    else {
        j -= NA;
        int w = j / NW; j -= w * NW;
        switch (w) {
            case 0: src = (const float4*)Wq; dst = (float4*)Wqt; break;
            case 1: src = (const float4*)Wk; dst = (float4*)Wkt; break;
            case 2: src = (const float4*)Wv; dst = (float4*)Wvt; break;
            default: if (w > 3) return;
                    src = (const float4*)Wo; dst = (float4*)Wot; break;
        }
    }
    dst[j] = cvt4(src[j]);
}

// ---------------------------------------------------------------------------
// tf32 GEMM (R13 core, STAGES=6): 128x128 tile, 4 warps, warp 64x64,
// BK=16 cp.async pipeline, full-stage fragment preload.
// ---------------------------------------------------------------------------
#define STAGES 6
#define GASTR 20
#define GBSTR 136
#define A_STG (128*GASTR)
#define B_STG (16*GBSTR)

__global__ __launch_bounds__(128, 2) void gemm_tf32(
    const float* __restrict__ A, const float* __restrict__ Bm,
    const float* __restrict__ bias, float* __restrict__ C,
    int M, int N, int K, float alpha, int round_out)
{
    extern __shared__ float smg[];
    float* As = smg;
    float* Bs = smg + STAGES * A_STG;

    const int tid  = threadIdx.x;
    const int warp = tid >> 5, lane = tid & 31;
    const int wm = warp >> 1, wn = warp & 1;
    const int g  = lane >> 2, tg = lane & 3;
    const int m0 = blockIdx.y * 128, n0 = blockIdx.x * 128;

    const int ar0 = tid >> 2, ac0 = (tid & 3) << 2;
    const int br0 = tid >> 5, bc0 = lane << 2;

    float acc[4][8][4];
#pragma unroll
    for (int mi = 0; mi < 4; mi++)
#pragma unroll
        for (int nj = 0; nj < 8; nj++)
#pragma unroll
            for (int r = 0; r < 4; r++) acc[mi][nj][r] = 0.f;

    const int nt = K >> 4;

    auto issue_tile = [&](int t, int stg) {
        const int k0 = t << 4;
        float* as = As + stg * A_STG;
        float* bs = Bs + stg * B_STG;
#pragma unroll
        for (int i = 0; i < 4; i++) {
            int ra = ar0 + i * 32;
            int gr = min(m0 + ra, M - 1);
            cp16(as + ra * GASTR + ac0, A + (size_t)gr * K + k0 + ac0);
            int rb = br0 + i * 4;
            cp16(bs + rb * GBSTR + bc0, Bm + (size_t)(k0 + rb) * N + n0 + bc0);
        }
    };

#pragma unroll
    for (int t = 0; t < STAGES - 1; t++) {
        issue_tile(t, t);
        asm volatile("cp.async.commit_group;");
    }

    for (int t = 0; t < nt; t++) {
        asm volatile("cp.async.wait_group %0;" :: "n"(STAGES - 2));
        __syncthreads();

        const float* as = As + (t % STAGES) * A_STG;
        const float* bs = Bs + (t % STAGES) * B_STG;

        // ---- load ALL fragments for this stage (both kk halves) ----
        uint32_t af[2][4][4], bf[2][8][2];
#pragma unroll
        for (int h = 0; h < 2; h++) {
            const int kk = h * 8;
#pragma unroll
            for (int mi = 0; mi < 4; mi++) {
                int row = wm * 64 + mi * 16 + g;
                af[h][mi][0] = __float_as_uint(as[row * GASTR + kk + tg]);
                af[h][mi][1] = __float_as_uint(as[(row + 8) * GASTR + kk + tg]);
                af[h][mi][2] = __float_as_uint(as[row * GASTR + kk + tg + 4]);
                af[h][mi][3] = __float_as_uint(as[(row + 8) * GASTR + kk + tg + 4]);
            }
#pragma unroll
            for (int nj = 0; nj < 8; nj++) {
                int col = wn * 64 + nj * 8 + g;
                bf[h][nj][0] = __float_as_uint(bs[(kk + tg) * GBSTR + col]);
                bf[h][nj][1] = __float_as_uint(bs[(kk + tg + 4) * GBSTR + col]);
            }
        }

        if (t + STAGES - 1 < nt)
            issue_tile(t + STAGES - 1, (t + STAGES - 1) % STAGES);
        asm volatile("cp.async.commit_group;");

        // ---- uninterrupted 64-HMMA burst ----
#pragma unroll
        for (int h = 0; h < 2; h++)
#pragma unroll
            for (int mi = 0; mi < 4; mi++)
#pragma unroll
                for (int nj = 0; nj < 8; nj++)
                    mma8(acc[mi][nj], af[h][mi], bf[h][nj]);
    }

    // Epilogue
#pragma unroll
    for (int nj = 0; nj < 8; nj++) {
        int col = n0 + wn * 64 + nj * 8 + tg * 2;
        float2 bv = make_float2(0.f, 0.f);
        if (bias) bv = *(const float2*)(bias + col);
#pragma unroll
        for (int mi = 0; mi < 4; mi++) {
            int r0 = m0 + wm * 64 + mi * 16 + g;
            if (r0 < M) {
                float ox = (acc[mi][nj][0] + bv.x) * alpha;
                float oy = (acc[mi][nj][1] + bv.y) * alpha;
                if (round_out) { ox = __uint_as_float(f2tf32(ox)); oy = __uint_as_float(f2tf32(oy)); }
                *(float2*)(C + (size_t)r0 * N + col) = make_float2(ox, oy);
            }
            if (r0 + 8 < M) {
                float ox = (acc[mi][nj][2] + bv.x) * alpha;
                float oy = (acc[mi][nj][3] + bv.y) * alpha;
                if (round_out) { ox = __uint_as_float(f2tf32(ox)); oy = __uint_as_float(f2tf32(oy)); }
                *(float2*)(C + (size_t)(r0 + 8) * N + col) = make_float2(ox, oy);
            }
        }
    }
}

// ---------------------------------------------------------------------------
// tf32 flash attention (R13 attn core, now 3 CTAs/SM): 4 warps, warp owns
// 16 q-rows x 64 s-cols. cp.async K double-buffer / V single-buffer +
// ldmatrix Q/K/P frags.
// ---------------------------------------------------------------------------
#define KSTR 68
#define VSTR 72
#define PQSTR 68
#define NCHUNK ((SS + 63) / 64)   // 24

__global__ __launch_bounds__(128, 3) void attn_tf32(
    const float* __restrict__ q, const float* __restrict__ k,
    const float* __restrict__ v, float* __restrict__ qk_out,
    float* __restrict__ wv_out)
{
    extern __shared__ float sm[];
    float* Ks = sm;                    // [2][64][68]
    float* Vs = Ks + 2 * 64 * KSTR;    // [64][72]
    float* Ps = Vs + 64 * VSTR;        // [64][68]  (also Q staging)

    const int tid  = threadIdx.x;
    const int warp = tid >> 5, lane = tid & 31;
    const int g  = lane >> 2, tg = lane & 3;
    const int bh = blockIdx.y;
    const int b  = bh >> 4, h = bh & 15;
    const int t0 = blockIdx.x * 64;
    const int rw = warp * 16;
    const int grow0 = t0 + rw + g;

    const int sr = tid >> 4, scol4 = (tid & 15) << 2;

    const uint32_t ps_u = (uint32_t)__cvta_generic_to_shared((void*)Ps)
        + (((rw + (lane & 15)) * PQSTR + (lane >> 4) * 4) << 2);
    const uint32_t ks_base = (uint32_t)__cvta_generic_to_shared((void*)Ks)
        + ((((lane & 7) + ((lane & 16) ? 8 : 0)) * KSTR + ((lane & 8) ? 4 : 0)) << 2);

    auto issueK = [&](int s0, int buf) {
        float* dst = Ks + buf * 64 * KSTR;
#pragma unroll
        for (int i = 0; i < 8; i++) {
            int r = sr + i * 8;
            if (s0 + r < SS)
                cp16(dst + r * KSTR + scol4,
                     k + (size_t)(b * SS + s0 + r) * DD + h * DH + scol4);
        }
    };
    auto issueV = [&](int s0) {
#pragma unroll
        for (int i = 0; i < 8; i++) {
            int r = sr + i * 8;
            if (s0 + r < SS)
                cp16(Vs + r * VSTR + scol4,
                     v + (size_t)(b * SS + s0 + r) * DD + h * DH + scol4);
        }
    };

    // ---- stage Q through smem (already tf32), pull frags via ldmatrix ----
#pragma unroll
    for (int i = 0; i < 8; i++) {
        int idx = tid + i * 128;
        int r = idx >> 4, c = (idx & 15) << 2;
        float4 val = *(const float4*)(q + (size_t)(b * TT + t0 + r) * DD + h * DH + c);
        *(float4*)(Ps + r * PQSTR + c) = val;
    }
    __syncthreads();

    uint32_t qf[8][4];
#pragma unroll
    for (int kk = 0; kk < 8; kk++)
        ldsm4(qf[kk], ps_u + ((kk * 8) << 2));

    float o[8][4];
#pragma unroll
    for (int nj = 0; nj < 8; nj++)
#pragma unroll
        for (int r = 0; r < 4; r++) o[nj][r] = 0.f;

    float m0s = -INFINITY, m1s = -INFINITY, l0s = 0.f, l1s = 0.f;

    __syncthreads();

    issueK(0, 0);
    asm volatile("cp.async.commit_group;");

    for (int ci = 0; ci < NCHUNK; ci++) {
        const int s0 = ci * 64;
        const int sc = min(64, SS - s0);
        const uint32_t ks_u = ks_base + (uint32_t)((ci & 1) * 64 * KSTR * 4);

        issueV(s0);
        asm volatile("cp.async.commit_group;");
        if (ci + 1 < NCHUNK) issueK(s0 + 64, (ci + 1) & 1);
        asm volatile("cp.async.commit_group;");

        asm volatile("cp.async.wait_group %0;" :: "n"(2));   // K(ci) arrived
        __syncthreads();

        // ---- QK^T via ldmatrix K-frags ----
        float qa[8][4];
#pragma unroll
        for (int nj = 0; nj < 8; nj++)
#pragma unroll
            for (int r = 0; r < 4; r++) qa[nj][r] = 0.f;

#pragma unroll
        for (int kk = 0; kk < 8; kk++) {
            uint32_t bfr[4][4];
#pragma unroll
            for (int p = 0; p < 4; p++)
                ldsm4(bfr[p], ks_u + ((p * 16 * KSTR + kk * 8) << 2));
#pragma unroll
            for (int p = 0; p < 4; p++) {
                mma8(qa[2 * p],     qf[kk], &bfr[p][0]);
                mma8(qa[2 * p + 1], qf[kk], &bfr[p][2]);
            }
        }

        // ---- write raw logits; mask out-of-range ----
        {
            size_t rowbase = ((size_t)bh * TT + grow0) * SS + s0;
#pragma unroll
            for (int nj = 0; nj < 8; nj++) {
                int col = nj * 8 + tg * 2;
                if (col < sc) {
                    *(float2*)(qk_out + rowbase + col)          = make_float2(qa[nj][0], qa[nj][1]);
                    *(float2*)(qk_out + rowbase + 8 * SS + col) = make_float2(qa[nj][2], qa[nj][3]);
                } else {
                    qa[nj][0] = qa[nj][1] = -1e30f;
                    qa[nj][2] = qa[nj][3] = -1e30f;
                }
            }
        }

        // ---- warp-local online softmax ----
        float mx0 = -INFINITY, mx1 = -INFINITY;
#pragma unroll
        for (int nj = 0; nj < 8; nj++) {
            mx0 = fmaxf(mx0, fmaxf(qa[nj][0], qa[nj][1]));
            mx1 = fmaxf(mx1, fmaxf(qa[nj][2], qa[nj][3]));
        }
        mx0 = fmaxf(mx0, __shfl_xor_sync(0xffffffffu, mx0, 1));
        mx0 = fmaxf(mx0, __shfl_xor_sync(0xffffffffu, mx0, 2));
        mx1 = fmaxf(mx1, __shfl_xor_sync(0xffffffffu, mx1, 1));
        mx1 = fmaxf(mx1, __shfl_xor_sync(0xffffffffu, mx1, 2));

        float mn0 = fmaxf(m0s, mx0), mn1 = fmaxf(m1s, mx1);
        float c0 = __expf(m0s - mn0), c1 = __expf(m1s - mn1);
        m0s = mn0; m1s = mn1;

        float s0r = 0.f, s1r = 0.f;
#pragma unroll
        for (int nj = 0; nj < 8; nj++) {
            float p0 = __expf(qa[nj][0] - mn0);
            float p1 = __expf(qa[nj][1] - mn0);
            float p2 = __expf(qa[nj][2] - mn1);
            float p3 = __expf(qa[nj][3] - mn1);
            s0r += p0 + p1; s1r += p2 + p3;
            qa[nj][0] = __uint_as_float(f2tf32(p0));
            qa[nj][1] = __uint_as_float(f2tf32(p1));
            qa[nj][2] = __uint_as_float(f2tf32(p2));
            qa[nj][3] = __uint_as_float(f2tf32(p3));
        }
        s0r += __shfl_xor_sync(0xffffffffu, s0r, 1);
        s0r += __shfl_xor_sync(0xffffffffu, s0r, 2);
        s1r += __shfl_xor_sync(0xffffffffu, s1r, 1);
        s1r += __shfl_xor_sync(0xffffffffu, s1r, 2);
        l0s = l0s * c0 + s0r;
        l1s = l1s * c1 + s1r;

#pragma unroll
        for (int nj = 0; nj < 8; nj++) {
            o[nj][0] *= c0; o[nj][1] *= c0;
            o[nj][2] *= c1; o[nj][3] *= c1;
        }

        // ---- P -> per-warp smem slab ----
#pragma unroll
        for (int nj = 0; nj < 8; nj++) {
            int col = nj * 8 + tg * 2;
            *(float2*)(Ps + (rw + g) * PQSTR + col)     = make_float2(qa[nj][0], qa[nj][1]);
            *(float2*)(Ps + (rw + g + 8) * PQSTR + col) = make_float2(qa[nj][2], qa[nj][3]);
        }
        __syncwarp();

        asm volatile("cp.async.wait_group %0;" :: "n"(1));   // V(ci) arrived
        __syncthreads();

        // ---- PV: A-frags via ldmatrix on Ps, V-frags plain LDS ----
#pragma unroll
        for (int kk = 0; kk < 8; kk++) {
            uint32_t af[4], bfr[8][2];
            ldsm4(af, ps_u + ((kk * 8) << 2));
#pragma unroll
            for (int nj = 0; nj < 8; nj++) {
                int dcol = nj * 8 + g;
                bfr[nj][0] = __float_as_uint(Vs[(kk * 8 + tg) * VSTR + dcol]);
                bfr[nj][1] = __float_as_uint(Vs[(kk * 8 + tg + 4) * VSTR + dcol]);
            }
#pragma unroll
            for (int nj = 0; nj < 8; nj++)
                mma8(o[nj], af, bfr[nj]);
        }
        __syncthreads();
    }

    // ---- normalize, write wv (tf32-rounded: consumed by out-GEMM) ----
    float inv0 = 1.f / l0s, inv1 = 1.f / l1s;
    size_t obase = (size_t)(b * TT + grow0) * DD + h * DH;
#pragma unroll
    for (int nj = 0; nj < 8; nj++) {
        int col = nj * 8 + tg * 2;
        float2 r0 = make_float2(__uint_as_float(f2tf32(o[nj][0] * inv0)),
                                __uint_as_float(f2tf32(o[nj][1] * inv0)));
        float2 r1 = make_float2(__uint_as_float(f2tf32(o[nj][2] * inv1)),
                                __uint_as_float(f2tf32(o[nj][3] * inv1)));
        *(float2*)(wv_out + obase + col)          = r0;
        *(float2*)(wv_out + obase + 8 * DD + col) = r1;
    }
}

// ---------------------------------------------------------------------------
extern "C" void kernel_launch(void* const* d_in, const int* in_sizes, int n_in,
                              void* d_out, int out_size)
{
    const float* x  = (const float*)d_in[0];
    const float* xa = (const float*)d_in[1];
    const float* Wq = (const float*)d_in[2];
    const float* bq = (const float*)d_in[3];
    const float* Wk = (const float*)d_in[4];
    const float* Wv = (const float*)d_in[5];
    const float* bv = (const float*)d_in[6];
    const float* Wo = (const float*)d_in[7];
    const float* bo = (const float*)d_in[8];

    float* out = (float*)d_out;               // [8,448,1024]
    float* qk  = out + OUT_ELEMS;             // [8,16,448,1500]

    float *q_s, *k_s, *v_s, *wv_s, *xt, *xat, *Wqt, *Wkt, *Wvt, *Wot;
    cudaGetSymbolAddress((void**)&q_s,  g_q);
    cudaGetSymbolAddress((void**)&k_s,  g_k);
    cudaGetSymbolAddress((void**)&v_s,  g_v);
    cudaGetSymbolAddress((void**)&wv_s, g_wv);
    cudaGetSymbolAddress((void**)&xt,   g_xt);
    cudaGetSymbolAddress((void**)&xat,  g_xat);
    cudaGetSymbolAddress((void**)&Wqt,  g_Wqt);
    cudaGetSymbolAddress((void**)&Wkt,  g_Wkt);
    cudaGetSymbolAddress((void**)&Wvt,  g_Wvt);
    cudaGetSymbolAddress((void**)&Wot,  g_Wot);

    const float scale = 0.3535533905932738f;  // 64^-0.25

    // ---- single fused pre-round of all operands ----
    {
        const int thr = 256;
        int total = NX + NA + 4 * NW;
        cvt_all<<<(total + thr - 1) / thr, thr>>>(x, xt, xa, xat,
                                                  Wq, Wqt, Wk, Wkt, Wv, Wvt, Wo, Wot);
    }

    static const size_t gemm_smem = (size_t)(STAGES * (A_STG + B_STG)) * sizeof(float); // 113664
    cudaFuncSetAttribute(gemm_tf32, cudaFuncAttributeMaxDynamicSharedMemorySize, (int)gemm_smem);

    dim3 blk(128);
    gemm_tf32<<<dim3(DD/128, (BB*TT + 127)/128), blk, gemm_smem>>>(xt,  Wqt, bq,      q_s, BB*TT, DD, DD, scale, 1);
    gemm_tf32<<<dim3(DD/128, (BB*SS + 127)/128), blk, gemm_smem>>>(xat, Wkt, nullptr, k_s, BB*SS, DD, DD, scale, 1);
    gemm_tf32<<<dim3(DD/128, (BB*SS + 127)/128), blk, gemm_smem>>>(xat, Wvt, bv,      v_s, BB*SS, DD, DD, 1.0f, 1);

    static const size_t attn_smem =
        (2 * 64 * KSTR + 64 * VSTR + 64 * PQSTR) * sizeof(float);  // 70656
    cudaFuncSetAttribute(attn_tf32, cudaFuncAttributeMaxDynamicSharedMemorySize, (int)attn_smem);
    attn_tf32<<<dim3(TT/64, BB*HH), dim3(128), attn_smem>>>(q_s, k_s, v_s, qk, wv_s);

    gemm_tf32<<<dim3(DD/128, (BB*TT + 127)/128), blk, gemm_smem>>>(wv_s, Wot, bo, out, BB*TT, DD, DD, 1.0f, 0);
}

// round 16
// speedup vs baseline: 1.1512x; 1.1328x over previous
#include <cuda_runtime.h>
#include <math.h>
#include <stdint.h>

// Problem constants
#define BB 8
#define TT 448
#define SS 1500
#define DD 1024
#define HH 16
#define DH 64
#define OUT_ELEMS (BB*TT*DD)
#define M_QO (BB*TT)
#define M_KV (BB*SS)

// Scratch
__device__ float g_q  [BB*TT*DD];
__device__ float g_k  [BB*SS*DD];
__device__ float g_v  [BB*SS*DD];
__device__ float g_wv [BB*TT*DD];
__device__ float g_xt [BB*TT*DD];
__device__ float g_xat[BB*SS*DD];
__device__ float g_Wqt[DD*DD];
__device__ float g_Wkt[DD*DD];
__device__ float g_Wvt[DD*DD];
__device__ float g_Wot[DD*DD];

// ---------------------------------------------------------------------------
// helpers
// ---------------------------------------------------------------------------
__device__ __forceinline__ uint32_t f2tf32(float f) {
    uint32_t r;
    asm("cvt.rna.tf32.f32 %0, %1;" : "=r"(r) : "f"(f));
    return r;
}
__device__ __forceinline__ float4 cvt4(float4 v) {
    return make_float4(__uint_as_float(f2tf32(v.x)), __uint_as_float(f2tf32(v.y)),
                       __uint_as_float(f2tf32(v.z)), __uint_as_float(f2tf32(v.w)));
}
__device__ __forceinline__ void mma8(float* c, const uint32_t* a, const uint32_t* b) {
    asm volatile("mma.sync.aligned.m16n8k8.row.col.f32.tf32.tf32.f32 "
        "{%0,%1,%2,%3}, {%4,%5,%6,%7}, {%8,%9}, {%0,%1,%2,%3};"
        : "+f"(c[0]), "+f"(c[1]), "+f"(c[2]), "+f"(c[3])
        : "r"(a[0]), "r"(a[1]), "r"(a[2]), "r"(a[3]), "r"(b[0]), "r"(b[1]));
}
__device__ __forceinline__ void cp16(const float* s, const float* g) {
    uint32_t sa = (uint32_t)__cvta_generic_to_shared((void*)s);
    asm volatile("cp.async.cg.shared.global [%0], [%1], 16;" :: "r"(sa), "l"(g));
}
__device__ __forceinline__ void ldsm4(uint32_t* r, uint32_t saddr) {
    asm volatile("ldmatrix.sync.aligned.m8n8.x4.shared.b16 {%0,%1,%2,%3}, [%4];"
        : "=r"(r[0]), "=r"(r[1]), "=r"(r[2]), "=r"(r[3]) : "r"(saddr));
}

// ---------------------------------------------------------------------------
// Single fused tf32 pre-round for all 6 operand tensors (elementwise).
// ---------------------------------------------------------------------------
#define NX (BB*TT*DD/4)
#define NA (BB*SS*DD/4)
#define NW (DD*DD/4)

__global__ void cvt_all(const float* __restrict__ x,  float* __restrict__ xt,
                        const float* __restrict__ xa, float* __restrict__ xat,
                        const float* __restrict__ Wq, float* __restrict__ Wqt,
                        const float* __restrict__ Wk, float* __restrict__ Wkt,
                        const float* __restrict__ Wv, float* __restrict__ Wvt,
                        const float* __restrict__ Wo, float* __restrict__ Wot)
{
    int i = blockIdx.x * blockDim.x + threadIdx.x;
    const float4* src; float4* dst; int j = i;
    if (j < NX)            { src = (const float4*)x;  dst = (float4*)xt; }
    else if ((j -= NX) < NA) { src = (const float4*)xa; dst = (float4*)xat; }
    else {
        j -= NA;
        int w = j / NW; j -= w * NW;
        switch (w) {
            case 0: src = (const float4*)Wq; dst = (float4*)Wqt; break;
            case 1: src = (const float4*)Wk; dst = (float4*)Wkt; break;
            case 2: src = (const float4*)Wv; dst = (float4*)Wvt; break;
            default: if (w > 3) return;
                    src = (const float4*)Wo; dst = (float4*)Wot; break;
        }
    }
    dst[j] = cvt4(src[j]);
}

// ---------------------------------------------------------------------------
// tf32 GEMM core (R13 + ldsm4 A-frags): 128x128 tile, 4 warps, warp 64x64,
// BK=16 cp.async pipeline, full-stage fragment preload.
// ---------------------------------------------------------------------------
#define STAGES 5
#define GASTR 20
#define GBSTR 136
#define A_STG (128*GASTR)
#define B_STG (16*GBSTR)

__device__ __forceinline__ void gemm_body(
    const float* __restrict__ A, const float* __restrict__ Bm,
    const float* __restrict__ bias, float* __restrict__ C,
    int M, int N, int K, float alpha, int round_out,
    float* As, float* Bs, int m0, int n0)
{
    const int tid  = threadIdx.x;
    const int warp = tid >> 5, lane = tid & 31;
    const int wm = warp >> 1, wn = warp & 1;
    const int g  = lane >> 2, tg = lane & 3;

    const int ar0 = tid >> 2, ac0 = (tid & 3) << 2;
    const int br0 = tid >> 5, bc0 = lane << 2;

    float acc[4][8][4];
#pragma unroll
    for (int mi = 0; mi < 4; mi++)
#pragma unroll
        for (int nj = 0; nj < 8; nj++)
#pragma unroll
            for (int r = 0; r < 4; r++) acc[mi][nj][r] = 0.f;

    const int nt = K >> 4;

    auto issue_tile = [&](int t, int stg) {
        const int k0 = t << 4;
        float* as = As + stg * A_STG;
        float* bs = Bs + stg * B_STG;
#pragma unroll
        for (int i = 0; i < 4; i++) {
            int ra = ar0 + i * 32;
            int gr = min(m0 + ra, M - 1);
            cp16(as + ra * GASTR + ac0, A + (size_t)gr * K + k0 + ac0);
            int rb = br0 + i * 4;
            cp16(bs + rb * GBSTR + bc0, Bm + (size_t)(k0 + rb) * N + n0 + bc0);
        }
    };

#pragma unroll
    for (int t = 0; t < STAGES - 1; t++) {
        issue_tile(t, t);
        asm volatile("cp.async.commit_group;");
    }

    // ldmatrix per-lane A offset (floats): rows (lane&15), word half (lane>>4)*4
    const int a_off = (wm * 64 + (lane & 15)) * GASTR + (lane >> 4) * 4;

    for (int t = 0; t < nt; t++) {
        asm volatile("cp.async.wait_group %0;" :: "n"(STAGES - 2));
        __syncthreads();

        const float* as = As + (t % STAGES) * A_STG;
        const float* bs = Bs + (t % STAGES) * B_STG;
        const uint32_t a_u = (uint32_t)__cvta_generic_to_shared((void*)as) + (a_off << 2);

        // ---- load ALL fragments for this stage (both kk halves) ----
        uint32_t af[2][4][4], bf[2][8][2];
#pragma unroll
        for (int h = 0; h < 2; h++) {
#pragma unroll
            for (int mi = 0; mi < 4; mi++)
                ldsm4(af[h][mi], a_u + ((mi * 16 * GASTR + h * 8) << 2));
#pragma unroll
            for (int nj = 0; nj < 8; nj++) {
                int col = wn * 64 + nj * 8 + g;
                bf[h][nj][0] = __float_as_uint(bs[(h * 8 + tg) * GBSTR + col]);
                bf[h][nj][1] = __float_as_uint(bs[(h * 8 + tg + 4) * GBSTR + col]);
            }
        }

        if (t + STAGES - 1 < nt)
            issue_tile(t + STAGES - 1, (t + STAGES - 1) % STAGES);
        asm volatile("cp.async.commit_group;");

        // ---- uninterrupted 64-HMMA burst ----
#pragma unroll
        for (int h = 0; h < 2; h++)
#pragma unroll
            for (int mi = 0; mi < 4; mi++)
#pragma unroll
                for (int nj = 0; nj < 8; nj++)
                    mma8(acc[mi][nj], af[h][mi], bf[h][nj]);
    }

    // Epilogue
#pragma unroll
    for (int nj = 0; nj < 8; nj++) {
        int col = n0 + wn * 64 + nj * 8 + tg * 2;
        float2 bv = make_float2(0.f, 0.f);
        if (bias) bv = *(const float2*)(bias + col);
#pragma unroll
        for (int mi = 0; mi < 4; mi++) {
            int r0 = m0 + wm * 64 + mi * 16 + g;
            if (r0 < M) {
                float ox = (acc[mi][nj][0] + bv.x) * alpha;
                float oy = (acc[mi][nj][1] + bv.y) * alpha;
                if (round_out) { ox = __uint_as_float(f2tf32(ox)); oy = __uint_as_float(f2tf32(oy)); }
                *(float2*)(C + (size_t)r0 * N + col) = make_float2(ox, oy);
            }
            if (r0 + 8 < M) {
                float ox = (acc[mi][nj][2] + bv.x) * alpha;
                float oy = (acc[mi][nj][3] + bv.y) * alpha;
                if (round_out) { ox = __uint_as_float(f2tf32(ox)); oy = __uint_as_float(f2tf32(oy)); }
                *(float2*)(C + (size_t)(r0 + 8) * N + col) = make_float2(ox, oy);
            }
        }
    }
}

// Generic single GEMM (used for out projection)
__global__ __launch_bounds__(128, 2) void gemm_tf32(
    const float* __restrict__ A, const float* __restrict__ Bm,
    const float* __restrict__ bias, float* __restrict__ C,
    int M, int N, int K, float alpha, int round_out)
{
    extern __shared__ float smg[];
    gemm_body(A, Bm, bias, C, M, N, K, alpha, round_out,
              smg, smg + STAGES * A_STG, blockIdx.y * 128, blockIdx.x * 128);
}

// Fused Q/K/V projections in ONE launch: blockIdx.z selects the operand set.
// grid = (N/128, ceil(M_KV/128), 3); z=0 (Q) blocks past M_QO exit early.
__global__ __launch_bounds__(128, 2) void gemm_qkv(
    const float* __restrict__ xt,  const float* __restrict__ xat,
    const float* __restrict__ Wqt, const float* __restrict__ Wkt,
    const float* __restrict__ Wvt,
    const float* __restrict__ bq,  const float* __restrict__ bv,
    float* __restrict__ q_s, float* __restrict__ k_s, float* __restrict__ v_s,
    float scale)
{
    extern __shared__ float smg[];
    const int z  = blockIdx.z;
    const int m0 = blockIdx.y * 128;

    const float* A;  const float* Bm; const float* bias; float* C;
    int M; float alpha;
    if (z == 0)      { A = xt;  Bm = Wqt; bias = bq;      C = q_s; M = M_QO; alpha = scale; }
    else if (z == 1) { A = xat; Bm = Wkt; bias = nullptr; C = k_s; M = M_KV; alpha = scale; }
    else             { A = xat; Bm = Wvt; bias = bv;      C = v_s; M = M_KV; alpha = 1.0f; }

    if (m0 >= M) return;
    gemm_body(A, Bm, bias, C, M, DD, DD, alpha, 1,
              smg, smg + STAGES * A_STG, m0, blockIdx.x * 128);
}

// ---------------------------------------------------------------------------
// tf32 flash attention (R13/R15 measured-best): 4 warps, warp owns 16 q-rows.
// cp.async K double-buffer / V single-buffer + ldmatrix Q/K/P frags.
// ---------------------------------------------------------------------------
#define KSTR 68
#define VSTR 72
#define PQSTR 68
#define NCHUNK ((SS + 63) / 64)   // 24

__global__ __launch_bounds__(128, 3) void attn_tf32(
    const float* __restrict__ q, const float* __restrict__ k,
    const float* __restrict__ v, float* __restrict__ qk_out,
    float* __restrict__ wv_out)
{
    extern __shared__ float sm[];
    float* Ks = sm;                    // [2][64][68]
    float* Vs = Ks + 2 * 64 * KSTR;    // [64][72]
    float* Ps = Vs + 64 * VSTR;        // [64][68]  (also Q staging)

    const int tid  = threadIdx.x;
    const int warp = tid >> 5, lane = tid & 31;
    const int g  = lane >> 2, tg = lane & 3;
    const int bh = blockIdx.y;
    const int b  = bh >> 4, h = bh & 15;
    const int t0 = blockIdx.x * 64;
    const int rw = warp * 16;
    const int grow0 = t0 + rw + g;

    const int sr = tid >> 4, scol4 = (tid & 15) << 2;

    const uint32_t ps_u = (uint32_t)__cvta_generic_to_shared((void*)Ps)
        + (((rw + (lane & 15)) * PQSTR + (lane >> 4) * 4) << 2);
    const uint32_t ks_base = (uint32_t)__cvta_generic_to_shared((void*)Ks)
        + ((((lane & 7) + ((lane & 16) ? 8 : 0)) * KSTR + ((lane & 8) ? 4 : 0)) << 2);

    auto issueK = [&](int s0, int buf) {
        float* dst = Ks + buf * 64 * KSTR;
#pragma unroll
        for (int i = 0; i < 8; i++) {
            int r = sr + i * 8;
            if (s0 + r < SS)
                cp16(dst + r * KSTR + scol4,
                     k + (size_t)(b * SS + s0 + r) * DD + h * DH + scol4);
        }
    };
    auto issueV = [&](int s0) {
#pragma unroll
        for (int i = 0; i < 8; i++) {
            int r = sr + i * 8;
            if (s0 + r < SS)
                cp16(Vs + r * VSTR + scol4,
                     v + (size_t)(b * SS + s0 + r) * DD + h * DH + scol4);
        }
    };

    // ---- stage Q through smem (already tf32), pull frags via ldmatrix ----
#pragma unroll
    for (int i = 0; i < 8; i++) {
        int idx = tid + i * 128;
        int r = idx >> 4, c = (idx & 15) << 2;
        float4 val = *(const float4*)(q + (size_t)(b * TT + t0 + r) * DD + h * DH + c);
        *(float4*)(Ps + r * PQSTR + c) = val;
    }
    __syncthreads();

    uint32_t qf[8][4];
#pragma unroll
    for (int kk = 0; kk < 8; kk++)
        ldsm4(qf[kk], ps_u + ((kk * 8) << 2));

    float o[8][4];
#pragma unroll
    for (int nj = 0; nj < 8; nj++)
#pragma unroll
        for (int r = 0; r < 4; r++) o[nj][r] = 0.f;

    float m0s = -INFINITY, m1s = -INFINITY, l0s = 0.f, l1s = 0.f;

    __syncthreads();

    issueK(0, 0);
    asm volatile("cp.async.commit_group;");

    for (int ci = 0; ci < NCHUNK; ci++) {
        const int s0 = ci * 64;
        const int sc = min(64, SS - s0);
        const uint32_t ks_u = ks_base + (uint32_t)((ci & 1) * 64 * KSTR * 4);

        issueV(s0);
        asm volatile("cp.async.commit_group;");
        if (ci + 1 < NCHUNK) issueK(s0 + 64, (ci + 1) & 1);
        asm volatile("cp.async.commit_group;");

        asm volatile("cp.async.wait_group %0;" :: "n"(2));   // K(ci) arrived
        __syncthreads();

        // ---- QK^T via ldmatrix K-frags ----
        float qa[8][4];
#pragma unroll
        for (int nj = 0; nj < 8; nj++)
#pragma unroll
            for (int r = 0; r < 4; r++) qa[nj][r] = 0.f;

#pragma unroll
        for (int kk = 0; kk < 8; kk++) {
            uint32_t bfr[4][4];
#pragma unroll
            for (int p = 0; p < 4; p++)
                ldsm4(bfr[p], ks_u + ((p * 16 * KSTR + kk * 8) << 2));
#pragma unroll
            for (int p = 0; p < 4; p++) {
                mma8(qa[2 * p],     qf[kk], &bfr[p][0]);
                mma8(qa[2 * p + 1], qf[kk], &bfr[p][2]);
            }
        }

        // ---- write raw logits; mask out-of-range ----
        {
            size_t rowbase = ((size_t)bh * TT + grow0) * SS + s0;
#pragma unroll
            for (int nj = 0; nj < 8; nj++) {
                int col = nj * 8 + tg * 2;
                if (col < sc) {
                    *(float2*)(qk_out + rowbase + col)          = make_float2(qa[nj][0], qa[nj][1]);
                    *(float2*)(qk_out + rowbase + 8 * SS + col) = make_float2(qa[nj][2], qa[nj][3]);
                } else {
                    qa[nj][0] = qa[nj][1] = -1e30f;
                    qa[nj][2] = qa[nj][3] = -1e30f;
                }
            }
        }

        // ---- warp-local online softmax ----
        float mx0 = -INFINITY, mx1 = -INFINITY;
#pragma unroll
        for (int nj = 0; nj < 8; nj++) {
            mx0 = fmaxf(mx0, fmaxf(qa[nj][0], qa[nj][1]));
            mx1 = fmaxf(mx1, fmaxf(qa[nj][2], qa[nj][3]));
        }
        mx0 = fmaxf(mx0, __shfl_xor_sync(0xffffffffu, mx0, 1));
        mx0 = fmaxf(mx0, __shfl_xor_sync(0xffffffffu, mx0, 2));
        mx1 = fmaxf(mx1, __shfl_xor_sync(0xffffffffu, mx1, 1));
        mx1 = fmaxf(mx1, __shfl_xor_sync(0xffffffffu, mx1, 2));

        float mn0 = fmaxf(m0s, mx0), mn1 = fmaxf(m1s, mx1);
        float c0 = __expf(m0s - mn0), c1 = __expf(m1s - mn1);
        m0s = mn0; m1s = mn1;

        float s0r = 0.f, s1r = 0.f;
#pragma unroll
        for (int nj = 0; nj < 8; nj++) {
            float p0 = __expf(qa[nj][0] - mn0);
            float p1 = __expf(qa[nj][1] - mn0);
            float p2 = __expf(qa[nj][2] - mn1);
            float p3 = __expf(qa[nj][3] - mn1);
            s0r += p0 + p1; s1r += p2 + p3;
            qa[nj][0] = __uint_as_float(f2tf32(p0));
            qa[nj][1] = __uint_as_float(f2tf32(p1));
            qa[nj][2] = __uint_as_float(f2tf32(p2));
            qa[nj][3] = __uint_as_float(f2tf32(p3));
        }
        s0r += __shfl_xor_sync(0xffffffffu, s0r, 1);
        s0r += __shfl_xor_sync(0xffffffffu, s0r, 2);
        s1r += __shfl_xor_sync(0xffffffffu, s1r, 1);
        s1r += __shfl_xor_sync(0xffffffffu, s1r, 2);
        l0s = l0s * c0 + s0r;
        l1s = l1s * c1 + s1r;

#pragma unroll
        for (int nj = 0; nj < 8; nj++) {
            o[nj][0] *= c0; o[nj][1] *= c0;
            o[nj][2] *= c1; o[nj][3] *= c1;
        }

        // ---- P -> per-warp smem slab ----
#pragma unroll
        for (int nj = 0; nj < 8; nj++) {
            int col = nj * 8 + tg * 2;
            *(float2*)(Ps + (rw + g) * PQSTR + col)     = make_float2(qa[nj][0], qa[nj][1]);
            *(float2*)(Ps + (rw + g + 8) * PQSTR + col) = make_float2(qa[nj][2], qa[nj][3]);
        }
        __syncwarp();

        asm volatile("cp.async.wait_group %0;" :: "n"(1));   // V(ci) arrived
        __syncthreads();

        // ---- PV: A-frags via ldmatrix on Ps, V-frags plain LDS ----
#pragma unroll
        for (int kk = 0; kk < 8; kk++) {
            uint32_t af[4], bfr[8][2];
            ldsm4(af, ps_u + ((kk * 8) << 2));
#pragma unroll
            for (int nj = 0; nj < 8; nj++) {
                int dcol = nj * 8 + g;
                bfr[nj][0] = __float_as_uint(Vs[(kk * 8 + tg) * VSTR + dcol]);
                bfr[nj][1] = __float_as_uint(Vs[(kk * 8 + tg + 4) * VSTR + dcol]);
            }
#pragma unroll
            for (int nj = 0; nj < 8; nj++)
                mma8(o[nj], af, bfr[nj]);
        }
        __syncthreads();
    }

    // ---- normalize, write wv (tf32-rounded: consumed by out-GEMM) ----
    float inv0 = 1.f / l0s, inv1 = 1.f / l1s;
    size_t obase = (size_t)(b * TT + grow0) * DD + h * DH;
#pragma unroll
    for (int nj = 0; nj < 8; nj++) {
        int col = nj * 8 + tg * 2;
        float2 r0 = make_float2(__uint_as_float(f2tf32(o[nj][0] * inv0)),
                                __uint_as_float(f2tf32(o[nj][1] * inv0)));
        float2 r1 = make_float2(__uint_as_float(f2tf32(o[nj][2] * inv1)),
                                __uint_as_float(f2tf32(o[nj][3] * inv1)));
        *(float2*)(wv_out + obase + col)          = r0;
        *(float2*)(wv_out + obase + 8 * DD + col) = r1;
    }
}

// ---------------------------------------------------------------------------
extern "C" void kernel_launch(void* const* d_in, const int* in_sizes, int n_in,
                              void* d_out, int out_size)
{
    const float* x  = (const float*)d_in[0];
    const float* xa = (const float*)d_in[1];
    const float* Wq = (const float*)d_in[2];
    const float* bq = (const float*)d_in[3];
    const float* Wk = (const float*)d_in[4];
    const float* Wv = (const float*)d_in[5];
    const float* bv = (const float*)d_in[6];
    const float* Wo = (const float*)d_in[7];
    const float* bo = (const float*)d_in[8];

    float* out = (float*)d_out;               // [8,448,1024]
    float* qk  = out + OUT_ELEMS;             // [8,16,448,1500]

    float *q_s, *k_s, *v_s, *wv_s, *xt, *xat, *Wqt, *Wkt, *Wvt, *Wot;
    cudaGetSymbolAddress((void**)&q_s,  g_q);
    cudaGetSymbolAddress((void**)&k_s,  g_k);
    cudaGetSymbolAddress((void**)&v_s,  g_v);
    cudaGetSymbolAddress((void**)&wv_s, g_wv);
    cudaGetSymbolAddress((void**)&xt,   g_xt);
    cudaGetSymbolAddress((void**)&xat,  g_xat);
    cudaGetSymbolAddress((void**)&Wqt,  g_Wqt);
    cudaGetSymbolAddress((void**)&Wkt,  g_Wkt);
    cudaGetSymbolAddress((void**)&Wvt,  g_Wvt);
    cudaGetSymbolAddress((void**)&Wot,  g_Wot);

    const float scale = 0.3535533905932738f;  // 64^-0.25

    // ---- single fused pre-round of all operands ----
    {
        const int thr = 256;
        int total = NX + NA + 4 * NW;
        cvt_all<<<(total + thr - 1) / thr, thr>>>(x, xt, xa, xat,
                                                  Wq, Wqt, Wk, Wkt, Wv, Wvt, Wo, Wot);
    }

    static const size_t gemm_smem = (size_t)(STAGES * (A_STG + B_STG)) * sizeof(float); // 94720
    cudaFuncSetAttribute(gemm_tf32, cudaFuncAttributeMaxDynamicSharedMemorySize, (int)gemm_smem);
    cudaFuncSetAttribute(gemm_qkv,  cudaFuncAttributeMaxDynamicSharedMemorySize, (int)gemm_smem);

    dim3 blk(128);
    // fused Q/K/V projections: one launch, z selects operand set
    gemm_qkv<<<dim3(DD/128, (M_KV + 127)/128, 3), blk, gemm_smem>>>(
        xt, xat, Wqt, Wkt, Wvt, bq, bv, q_s, k_s, v_s, scale);

    static const size_t attn_smem =
        (2 * 64 * KSTR + 64 * VSTR + 64 * PQSTR) * sizeof(float);  // 70656
    cudaFuncSetAttribute(attn_tf32, cudaFuncAttributeMaxDynamicSharedMemorySize, (int)attn_smem);
    attn_tf32<<<dim3(TT/64, BB*HH), dim3(128), attn_smem>>>(q_s, k_s, v_s, qk, wv_s);

    gemm_tf32<<<dim3(DD/128, (M_QO + 127)/128), blk, gemm_smem>>>(wv_s, Wot, bo, out, M_QO, DD, DD, 1.0f, 0);
}